// round 1
// baseline (speedup 1.0000x reference)
#include <cuda_runtime.h>

// selfAttn2d: per-patch fused attention. One CTA per patch (4096 patches).
//
// Patch pb -> b = pb/1024, oy = (pb/32)%32, ox = pb%32.
// sp[c,i,j] = x[b,c, oy*2+i-1, ox*2+j-1] (zero OOB), i,j in [0,4).
//
// Phases:
//  0: load sp_pad[64][6][6] (zero ring for the per-patch 3x3 conv) + sp_lin[64][16]
//  1: q/k/v = W @ sp (q scaled 1/4)
//  2: rel_c[ch,ac] = 3x3 conv of sp with w_rel (per-patch zero padding)
//  3: rl[n,ac,bd] = sum_ch rel_c[ch,ac] * sum_e q[n,e,ac]*w_deconv[ch,n*16+e,bd]
//  4: logits = MLP(q_p,k_p) + rl; softmax over bd; attn; csum over (n,p_hi)
//  5: out[o] = sum_j csum[j]*w_proj[o,j] + 16*b_proj[o]

__global__ __launch_bounds__(256, 2)
void selfattn2d_kernel(const float* __restrict__ x,
                       const float* __restrict__ wq,
                       const float* __restrict__ wk,
                       const float* __restrict__ wv,
                       const float* __restrict__ w_rel,
                       const float* __restrict__ w_deconv,
                       const float* __restrict__ w_sf1,
                       const float* __restrict__ b_sf1,
                       const float* __restrict__ w_sf2,
                       const float* __restrict__ b_sf2,
                       const float* __restrict__ w_proj,
                       const float* __restrict__ b_proj,
                       float* __restrict__ out)
{
    // multi-purpose buffer:
    //   phases 0-2: sp_pad = smemA[0..2303] (64*36), sp_lin = smemA[2304..3327] (64*16)
    //   phase 3   : partial rel_logits [256][16]
    //   phase 4   : attn staging [64][16]
    __shared__ float smemA[4096];
    __shared__ float q_s[4][16][16];   // [n][e][ac]
    __shared__ float k_s[4][16][16];   // [n][d][p]
    __shared__ float v_s[4][16][16];   // [n][dv][m]
    __shared__ float relc_s[64][16];   // [ch][ac]
    __shared__ float rl_s[4][16][16];  // [n][bd][ac]
    __shared__ float csum[64];

    const int pb = blockIdx.x;
    const int b  = pb >> 10;
    const int oy = (pb >> 5) & 31;
    const int ox = pb & 31;
    const int t  = threadIdx.x;

    // ---------------- Phase 0: load patch ----------------
    {
        const float* xb = x + b * (64 * 64 * 64);
        for (int idx = t; idx < 64 * 36; idx += 256) {
            int c  = idx / 36;
            int r  = idx - c * 36;
            int ii = r / 6;
            int jj = r - ii * 6;
            int gy = oy * 2 + ii - 2;
            int gx = ox * 2 + jj - 2;
            float val = 0.f;
            bool inpatch = (ii >= 1 && ii <= 4 && jj >= 1 && jj <= 4);
            if (inpatch && gy >= 0 && gy < 64 && gx >= 0 && gx < 64)
                val = xb[c * 4096 + gy * 64 + gx];
            smemA[c * 36 + r] = val;
            if (inpatch)
                smemA[2304 + c * 16 + (ii - 1) * 4 + (jj - 1)] = val;
        }
    }
    __syncthreads();

    // ---------------- Phase 1: q / k / v ----------------
    if (t < 192) {
        const int m = t >> 6;   // 0=q 1=k 2=v
        const int o = t & 63;
        const float* W = (m == 0) ? wq : (m == 1) ? wk : wv;
        const float* spl = smemA + 2304;
        float acc[16];
#pragma unroll
        for (int i = 0; i < 16; i++) acc[i] = 0.f;
#pragma unroll 4
        for (int c = 0; c < 64; c++) {
            float w = W[o * 64 + c];
            const float4* sp4 = (const float4*)(spl + c * 16);
            float4 s0 = sp4[0], s1 = sp4[1], s2 = sp4[2], s3 = sp4[3];
            acc[0]  += w * s0.x; acc[1]  += w * s0.y; acc[2]  += w * s0.z; acc[3]  += w * s0.w;
            acc[4]  += w * s1.x; acc[5]  += w * s1.y; acc[6]  += w * s1.z; acc[7]  += w * s1.w;
            acc[8]  += w * s2.x; acc[9]  += w * s2.y; acc[10] += w * s2.z; acc[11] += w * s2.w;
            acc[12] += w * s3.x; acc[13] += w * s3.y; acc[14] += w * s3.z; acc[15] += w * s3.w;
        }
        const float scale = (m == 0) ? 0.25f : 1.0f;
        const int n = o >> 4, e = o & 15;
        float* dst = (m == 0) ? &q_s[n][e][0] : (m == 1) ? &k_s[n][e][0] : &v_s[n][e][0];
#pragma unroll
        for (int i = 0; i < 16; i++) dst[i] = acc[i] * scale;
    }

    // ---------------- Phase 2: rel_c (per-patch 3x3 conv) ----------------
    {
        const int ch = t >> 2;
        const int cp = t & 3;
        float acc[16];
#pragma unroll
        for (int i = 0; i < 16; i++) acc[i] = 0.f;
        for (int cc = 0; cc < 16; cc++) {
            const int c = cp * 16 + cc;
            const float* sp = smemA + c * 36;
            float sreg[36];
#pragma unroll
            for (int u = 0; u < 36; u++) sreg[u] = sp[u];
            const float* wr = w_rel + ch * 576 + c * 9;
            float w[9];
#pragma unroll
            for (int u = 0; u < 9; u++) w[u] = wr[u];
#pragma unroll
            for (int di = 0; di < 3; di++)
#pragma unroll
                for (int dj = 0; dj < 3; dj++) {
                    const float ww = w[di * 3 + dj];
#pragma unroll
                    for (int i = 0; i < 4; i++)
#pragma unroll
                        for (int j = 0; j < 4; j++)
                            acc[i * 4 + j] += ww * sreg[(i + di) * 6 + (j + dj)];
                }
        }
        // reduce the 4 c-quarters (consecutive lanes)
#pragma unroll
        for (int ac = 0; ac < 16; ac++) {
            float v = acc[ac];
            v += __shfl_down_sync(0xffffffffu, v, 1);
            v += __shfl_down_sync(0xffffffffu, v, 2);
            if (cp == 0) relc_s[ch][ac] = v;
        }
    }
    __syncthreads();

    // ---------------- Phase 3: fused rel + q contraction ----------------
    {
        const int bd = t & 15;
        const int n  = (t >> 4) & 3;
        const int eg = t >> 6;            // 4 e's per thread
        const int obase = n * 16 + eg * 4;
        float acc[16];
#pragma unroll
        for (int i = 0; i < 16; i++) acc[i] = 0.f;
        const float* wd0 = w_deconv + obase * 16 + bd;
        const float* qb  = &q_s[n][eg * 4][0];
#pragma unroll 2
        for (int ch = 0; ch < 64; ch++) {
            const float* wdc = wd0 + ch * 1024;
            float w0 = __ldg(wdc);
            float w1 = __ldg(wdc + 16);
            float w2 = __ldg(wdc + 32);
            float w3 = __ldg(wdc + 48);
            const float4* q0 = (const float4*)(qb);
            const float4* q1 = (const float4*)(qb + 16);
            const float4* q2 = (const float4*)(qb + 32);
            const float4* q3 = (const float4*)(qb + 48);
            const float4* rc = (const float4*)(&relc_s[ch][0]);
#pragma unroll
            for (int u = 0; u < 4; u++) {
                float4 a0 = q0[u], a1 = q1[u], a2 = q2[u], a3 = q3[u];
                float4 r  = rc[u];
                float t0 = w0 * a0.x + w1 * a1.x + w2 * a2.x + w3 * a3.x;
                float t1 = w0 * a0.y + w1 * a1.y + w2 * a2.y + w3 * a3.y;
                float t2 = w0 * a0.z + w1 * a1.z + w2 * a2.z + w3 * a3.z;
                float t3 = w0 * a0.w + w1 * a1.w + w2 * a2.w + w3 * a3.w;
                acc[u * 4 + 0] += r.x * t0;
                acc[u * 4 + 1] += r.y * t1;
                acc[u * 4 + 2] += r.z * t2;
                acc[u * 4 + 3] += r.w * t3;
            }
        }
#pragma unroll
        for (int ac = 0; ac < 16; ac++) smemA[t * 16 + ac] = acc[ac];
    }
    __syncthreads();
    // reduce over the 4 e-groups
    for (int u = t; u < 1024; u += 256) {
        const int nbd = u >> 4;         // n*16 + bd
        const int ac  = u & 15;
        float v = smemA[nbd * 16 + ac]
                + smemA[(64  + nbd) * 16 + ac]
                + smemA[(128 + nbd) * 16 + ac]
                + smemA[(192 + nbd) * 16 + ac];
        rl_s[nbd >> 4][nbd & 15][ac] = v;
    }
    __syncthreads();

    // ---------------- Phase 4: MLP + softmax + attention ----------------
    if (t < 64) {
        const int n = t >> 4;
        const int p = t & 15;
        float h1[16];
#pragma unroll
        for (int h = 0; h < 16; h++) {
            float s = b_sf1[h];
            const float* w1r = w_sf1 + h * 32;
#pragma unroll
            for (int d = 0; d < 16; d++) s += w1r[d] * q_s[n][d][p];
#pragma unroll
            for (int d = 0; d < 16; d++) s += w1r[16 + d] * k_s[n][d][p];
            h1[h] = tanhf(s);
        }
        float lg[16];
        float mx = -1e30f;
#pragma unroll
        for (int m = 0; m < 16; m++) {
            float s = b_sf2[m];
            const float* w2r = w_sf2 + m * 16;
#pragma unroll
            for (int h = 0; h < 16; h++) s += w2r[h] * h1[h];
            s += rl_s[n][m][p];
            lg[m] = s;
            mx = fmaxf(mx, s);
        }
        float den = 0.f;
#pragma unroll
        for (int m = 0; m < 16; m++) { lg[m] = __expf(lg[m] - mx); den += lg[m]; }
        const float inv = 1.0f / den;
#pragma unroll
        for (int dv = 0; dv < 16; dv++) {
            float a = 0.f;
#pragma unroll
            for (int m = 0; m < 16; m++) a += lg[m] * v_s[n][dv][m];
            smemA[(n * 16 + p) * 16 + dv] = a * inv;  // attn staging
        }
    }
    __syncthreads();
    // csum[j = p_lo*16 + dv] = sum over (n, p_hi) of attn[n, p_hi*4+p_lo, dv]
    if (t < 64) {
        const int plo = t >> 4;
        const int dv  = t & 15;
        float s = 0.f;
#pragma unroll
        for (int n2 = 0; n2 < 4; n2++)
#pragma unroll
            for (int ph = 0; ph < 4; ph++)
                s += smemA[(n2 * 16 + ph * 4 + plo) * 16 + dv];
        csum[t] = s;
    }
    __syncthreads();

    // ---------------- Phase 5: projection + sum ----------------
    if (t < 64) {
        const int o = t;
        float acc = 16.0f * b_proj[o];
        const float* wp = w_proj + o * 64;
#pragma unroll 8
        for (int j = 0; j < 64; j++) acc += csum[j] * wp[j];
        out[b * 65536 + o * 1024 + oy * 32 + ox] = acc;
    }
}

extern "C" void kernel_launch(void* const* d_in, const int* in_sizes, int n_in,
                              void* d_out, int out_size)
{
    (void)in_sizes; (void)n_in; (void)out_size;
    selfattn2d_kernel<<<4096, 256>>>(
        (const float*)d_in[0],  // x
        (const float*)d_in[1],  // wq
        (const float*)d_in[2],  // wk
        (const float*)d_in[3],  // wv
        (const float*)d_in[4],  // w_rel
        (const float*)d_in[5],  // w_deconv
        (const float*)d_in[6],  // w_sf1
        (const float*)d_in[7],  // b_sf1
        (const float*)d_in[8],  // w_sf2
        (const float*)d_in[9],  // b_sf2
        (const float*)d_in[10], // w_proj
        (const float*)d_in[11], // b_proj
        (float*)d_out);
}

// round 2
// speedup vs baseline: 1.7716x; 1.7716x over previous
#include <cuda_runtime.h>

// selfAttn2d, round 2: coalesced transposed weights + f32x2 packed math +
// register-cached q in the dominant contraction.

typedef unsigned long long u64;

__device__ __forceinline__ u64 pack2(float lo, float hi) {
    u64 r; asm("mov.b64 %0,{%1,%2};" : "=l"(r) : "f"(lo), "f"(hi)); return r;
}
__device__ __forceinline__ void unpack2(u64 v, float& lo, float& hi) {
    asm("mov.b64 {%0,%1},%2;" : "=f"(lo), "=f"(hi) : "l"(v));
}
__device__ __forceinline__ u64 ffma2(u64 a, u64 b, u64 c) {
    u64 d; asm("fma.rn.f32x2 %0,%1,%2,%3;" : "=l"(d) : "l"(a), "l"(b), "l"(c)); return d;
}
__device__ __forceinline__ u64 fmul2(u64 a, u64 b) {
    u64 d; asm("mul.rn.f32x2 %0,%1,%2;" : "=l"(d) : "l"(a), "l"(b)); return d;
}
__device__ __forceinline__ u64 fadd2(u64 a, u64 b) {
    u64 d; asm("add.rn.f32x2 %0,%1,%2;" : "=l"(d) : "l"(a), "l"(b)); return d;
}

// Transposed weights (filled by prep_kernel each launch).
__device__ float g_wqt[64 * 64];    // [c][o]
__device__ float g_wkt[64 * 64];
__device__ float g_wvt[64 * 64];
__device__ float g_wpt[64 * 64];    // w_proj [j][o]
__device__ float g_wrt[576 * 64];   // w_rel  [(c*9+u)][ch]

__global__ void prep_kernel(const float* __restrict__ wq,
                            const float* __restrict__ wk,
                            const float* __restrict__ wv,
                            const float* __restrict__ w_rel,
                            const float* __restrict__ w_proj)
{
    const int i0 = blockIdx.x * blockDim.x + threadIdx.x;
    const int stride = gridDim.x * blockDim.x;
    for (int i = i0; i < 4096; i += stride) {
        int o = i >> 6, c = i & 63;
        int d = (c << 6) | o;
        g_wqt[d] = wq[i];
        g_wkt[d] = wk[i];
        g_wvt[d] = wv[i];
        g_wpt[d] = w_proj[i];
    }
    for (int j = i0; j < 36864; j += stride) {
        int ch = j / 576, r = j - ch * 576;
        g_wrt[r * 64 + ch] = w_rel[j];
    }
}

__global__ __launch_bounds__(256, 2)
void selfattn2d_kernel(const float* __restrict__ x,
                       const float* __restrict__ w_deconv,
                       const float* __restrict__ w_sf1,
                       const float* __restrict__ b_sf1,
                       const float* __restrict__ w_sf2,
                       const float* __restrict__ b_sf2,
                       const float* __restrict__ b_proj,
                       float* __restrict__ out)
{
    // smemA usage:
    //   phases 0-2: sp_pad[64][6][8] = smemA[0..3071], sp_lin[64][16] = smemA[3072..4095]
    //   phase 3   : packed partials (2048 u64)
    //   phase 4   : attn staging [64][16]
    __shared__ __align__(16) float smemA[4096];
    __shared__ __align__(16) float q_s[4][16][16];   // [n][e][ac]
    __shared__ __align__(16) float k_s[4][16][16];
    __shared__ __align__(16) float v_s[4][16][16];
    __shared__ __align__(16) float relc_s[64][16];   // [ch][ac]
    __shared__ __align__(16) float rl_s[4][16][16];  // [n][bd][ac]
    __shared__ float csum[64];

    const int pb = blockIdx.x;
    const int b  = pb >> 10;
    const int oy = (pb >> 5) & 31;
    const int ox = pb & 31;
    const int t  = threadIdx.x;

    // ---------------- Phase 0: load patch ----------------
    {
        const float* xb = x + b * (64 * 64 * 64);
        for (int idx = t; idx < 64 * 48; idx += 256) {
            int c  = idx / 48;
            int r  = idx - c * 48;
            int ii = r >> 3;
            int jj = r & 7;
            int gy = oy * 2 + ii - 2;
            int gx = ox * 2 + jj - 2;
            float val = 0.f;
            bool inpatch = (ii >= 1 && ii <= 4 && jj >= 1 && jj <= 4);
            if (inpatch && gy >= 0 && gy < 64 && gx >= 0 && gx < 64)
                val = xb[c * 4096 + gy * 64 + gx];
            smemA[idx] = val;
            if (inpatch)
                smemA[3072 + c * 16 + (ii - 1) * 4 + (jj - 1)] = val;
        }
    }
    __syncthreads();

    // ---------------- Phase 1: q / k / v (coalesced + f32x2) ----------------
    if (t < 192) {
        const int m = t >> 6;   // 0=q 1=k 2=v
        const int o = t & 63;
        const float* Wt = (m == 0) ? g_wqt : (m == 1) ? g_wkt : g_wvt;
        const u64* spl = (const u64*)(smemA + 3072);
        u64 acc2[8];
#pragma unroll
        for (int p = 0; p < 8; p++) acc2[p] = 0ull;
#pragma unroll 4
        for (int c = 0; c < 64; c++) {
            float w = Wt[(c << 6) | o];
            u64 w2 = pack2(w, w);
            const u64* row = spl + c * 8;
#pragma unroll
            for (int p = 0; p < 8; p++) acc2[p] = ffma2(w2, row[p], acc2[p]);
        }
        const int n = o >> 4, e = o & 15;
        u64* dst = (m == 0) ? (u64*)&q_s[n][e][0] : (m == 1) ? (u64*)&k_s[n][e][0] : (u64*)&v_s[n][e][0];
        if (m == 0) {
            const u64 s2 = pack2(0.25f, 0.25f);
#pragma unroll
            for (int p = 0; p < 8; p++) dst[p] = fmul2(acc2[p], s2);
        } else {
#pragma unroll
            for (int p = 0; p < 8; p++) dst[p] = acc2[p];
        }
    }

    // ---------------- Phase 2: rel_c (3x3 conv, f32x2) ----------------
    {
        const int ch = t >> 2;
        const int cp = t & 3;
        u64 acc2[8];   // [i][jp]
#pragma unroll
        for (int p = 0; p < 8; p++) acc2[p] = 0ull;
        for (int cc = 0; cc < 16; cc++) {
            const int c = cp * 16 + cc;
            const u64* row = (const u64*)(smemA + c * 48);
            u64 A[6][3], B[6][2];
#pragma unroll
            for (int r = 0; r < 6; r++) {
                A[r][0] = row[r * 4 + 0];
                A[r][1] = row[r * 4 + 1];
                A[r][2] = row[r * 4 + 2];
                float s0, s1, s2, s3, s4, s5;
                unpack2(A[r][0], s0, s1);
                unpack2(A[r][1], s2, s3);
                unpack2(A[r][2], s4, s5);
                B[r][0] = pack2(s1, s2);
                B[r][1] = pack2(s3, s4);
            }
            const float* wr = g_wrt + c * 9 * 64 + ch;
            float wf[9];
#pragma unroll
            for (int u = 0; u < 9; u++) wf[u] = wr[u * 64];
#pragma unroll
            for (int di = 0; di < 3; di++) {
#pragma unroll
                for (int dj = 0; dj < 3; dj++) {
                    const u64 w2 = pack2(wf[di * 3 + dj], wf[di * 3 + dj]);
#pragma unroll
                    for (int i = 0; i < 4; i++) {
                        const int r = i + di;
                        u64 X0 = (dj == 0) ? A[r][0] : (dj == 1) ? B[r][0] : A[r][1];
                        u64 X1 = (dj == 0) ? A[r][1] : (dj == 1) ? B[r][1] : A[r][2];
                        acc2[i * 2 + 0] = ffma2(w2, X0, acc2[i * 2 + 0]);
                        acc2[i * 2 + 1] = ffma2(w2, X1, acc2[i * 2 + 1]);
                    }
                }
            }
        }
        // reduce the 4 c-quarters (consecutive lanes), packed adds
#pragma unroll
        for (int p = 0; p < 8; p++) {
            u64 v = acc2[p];
            v = fadd2(v, __shfl_down_sync(0xffffffffu, v, 1));
            v = fadd2(v, __shfl_down_sync(0xffffffffu, v, 2));
            if (cp == 0) ((u64*)&relc_s[ch][0])[p] = v;
        }
    }
    __syncthreads();

    // ---------------- Phase 3: fused rel + q contraction (q in regs, f32x2) ----------------
    {
        const int bd = t & 15;
        const int n  = (t >> 4) & 3;
        const int eg = t >> 6;            // 4 e's per thread
        // preload q pairs: loop-invariant over ch
        u64 q2[32];
#pragma unroll
        for (int e = 0; e < 4; e++) {
            const u64* qr = (const u64*)&q_s[n][eg * 4 + e][0];
#pragma unroll
            for (int p = 0; p < 8; p++) q2[e * 8 + p] = qr[p];
        }
        u64 acc2[8];
#pragma unroll
        for (int p = 0; p < 8; p++) acc2[p] = 0ull;
        const float* wd0 = w_deconv + (n * 16 + eg * 4) * 16 + bd;
#pragma unroll 2
        for (int ch = 0; ch < 64; ch++) {
            const float* wdc = wd0 + ch * 1024;
            float w0 = __ldg(wdc);
            float w1 = __ldg(wdc + 16);
            float w2 = __ldg(wdc + 32);
            float w3 = __ldg(wdc + 48);
            u64 W0 = pack2(w0, w0), W1 = pack2(w1, w1), W2 = pack2(w2, w2), W3 = pack2(w3, w3);
            const u64* rc = (const u64*)&relc_s[ch][0];
#pragma unroll
            for (int p = 0; p < 8; p++) {
                u64 tv = fmul2(W0, q2[p]);
                tv = ffma2(W1, q2[8 + p], tv);
                tv = ffma2(W2, q2[16 + p], tv);
                tv = ffma2(W3, q2[24 + p], tv);
                acc2[p] = ffma2(rc[p], tv, acc2[p]);
            }
        }
        u64* part = (u64*)smemA;
#pragma unroll
        for (int p = 0; p < 8; p++) part[t * 8 + p] = acc2[p];
    }
    __syncthreads();
    // reduce over the 4 e-groups (packed)
    {
        const u64* part = (const u64*)smemA;
        for (int v = t; v < 512; v += 256) {
            const int nbd = v >> 3;
            const int p   = v & 7;
            u64 s = part[nbd * 8 + p];
            s = fadd2(s, part[(64  + nbd) * 8 + p]);
            s = fadd2(s, part[(128 + nbd) * 8 + p]);
            s = fadd2(s, part[(192 + nbd) * 8 + p]);
            ((u64*)&rl_s[nbd >> 4][nbd & 15][0])[p] = s;
        }
    }
    __syncthreads();

    // ---------------- Phase 4: MLP + softmax + attention ----------------
    if (t < 64) {
        const int n = t >> 4;
        const int p = t & 15;
        float h1[16];
#pragma unroll
        for (int h = 0; h < 16; h++) {
            float s = b_sf1[h];
            const float* w1r = w_sf1 + h * 32;
#pragma unroll
            for (int d = 0; d < 16; d++) s += w1r[d] * q_s[n][d][p];
#pragma unroll
            for (int d = 0; d < 16; d++) s += w1r[16 + d] * k_s[n][d][p];
            h1[h] = tanhf(s);
        }
        float lg[16];
        float mx = -1e30f;
#pragma unroll
        for (int m = 0; m < 16; m++) {
            float s = b_sf2[m];
            const float* w2r = w_sf2 + m * 16;
#pragma unroll
            for (int h = 0; h < 16; h++) s += w2r[h] * h1[h];
            s += rl_s[n][m][p];
            lg[m] = s;
            mx = fmaxf(mx, s);
        }
        float den = 0.f;
#pragma unroll
        for (int m = 0; m < 16; m++) { lg[m] = __expf(lg[m] - mx); den += lg[m]; }
        const float inv = 1.0f / den;
#pragma unroll
        for (int dv = 0; dv < 16; dv++) {
            float a = 0.f;
#pragma unroll
            for (int m = 0; m < 16; m++) a += lg[m] * v_s[n][dv][m];
            smemA[(n * 16 + p) * 16 + dv] = a * inv;
        }
    }
    __syncthreads();
    // csum[j = p_lo*16 + dv] = sum over (n, p_hi) of attn[n, p_hi*4+p_lo, dv]
    if (t < 64) {
        const int plo = t >> 4;
        const int dv  = t & 15;
        float s = 0.f;
#pragma unroll
        for (int n2 = 0; n2 < 4; n2++)
#pragma unroll
            for (int ph = 0; ph < 4; ph++)
                s += smemA[(n2 * 16 + ph * 4 + plo) * 16 + dv];
        csum[t] = s;
    }
    __syncthreads();

    // ---------------- Phase 5: projection + sum (coalesced) ----------------
    if (t < 64) {
        const int o = t;
        float acc = 16.0f * b_proj[o];
#pragma unroll 8
        for (int j = 0; j < 64; j++) acc += csum[j] * g_wpt[(j << 6) | o];
        out[b * 65536 + o * 1024 + oy * 32 + ox] = acc;
    }
}

extern "C" void kernel_launch(void* const* d_in, const int* in_sizes, int n_in,
                              void* d_out, int out_size)
{
    (void)in_sizes; (void)n_in; (void)out_size;
    prep_kernel<<<64, 256>>>(
        (const float*)d_in[1],  // wq
        (const float*)d_in[2],  // wk
        (const float*)d_in[3],  // wv
        (const float*)d_in[4],  // w_rel
        (const float*)d_in[10]);// w_proj
    selfattn2d_kernel<<<4096, 256>>>(
        (const float*)d_in[0],  // x
        (const float*)d_in[5],  // w_deconv
        (const float*)d_in[6],  // w_sf1
        (const float*)d_in[7],  // b_sf1
        (const float*)d_in[8],  // w_sf2
        (const float*)d_in[9],  // b_sf2
        (const float*)d_in[11], // b_proj
        (float*)d_out);
}